// round 14
// baseline (speedup 1.0000x reference)
#include <cuda_runtime.h>
#include <cuda_fp16.h>
#include <cstdint>
#include <math_constants.h>

#define NV   4096
#define DV   256
#define TK   20
#define TKI  10
#define NSEL 30
#define MLAB 5
#define NW   (NV/32)
#define NI   26
#define NE   14
#define NC   (NI + NE)
#define FB   (1u << 28)

typedef unsigned long long ull;

// -------- scratch (static device globals; no allocation) --------
__device__ __half   g_Eh[(size_t)NV * DV];         // 2 MB fp16 copy of E
__device__ unsigned short g_p16[(size_t)NV * NV];  // 32 MB packed coarse keys
__device__ int      g_cand[NV * NC];
__device__ int      g_knn[NV * NSEL];
__device__ unsigned g_bits[NV * NW];

// ============================================================================
// Phase 0: one-shot fp32 -> fp16 conversion of E (L2-resident afterwards)
// ============================================================================
__global__ void __launch_bounds__(256) conv_kernel(const float* __restrict__ E) {
    int idx = blockIdx.x * 256 + threadIdx.x;      // 131072 threads, 8 floats each
    const float4* src = (const float4*)E + idx * 2;
    float4 v0 = __ldg(src);
    float4 v1 = __ldg(src + 1);
    uint4 u;
    __half2 h;
    h = __floats2half2_rn(v0.x, v0.y); u.x = *(uint32_t*)&h;
    h = __floats2half2_rn(v0.z, v0.w); u.y = *(uint32_t*)&h;
    h = __floats2half2_rn(v1.x, v1.y); u.z = *(uint32_t*)&h;
    h = __floats2half2_rn(v1.z, v1.w); u.w = *(uint32_t*)&h;
    *((uint4*)g_Eh + idx) = u;
}

// ============================================================================
// Phase 1: coarse sim via fp16 mma.sync m16n8k16. cp.async feed (no converts,
// no register round-trip), ldmatrix fragments, double-buffered.
// ============================================================================
#define SL2 40                          // slab row stride in halves
#define SLABH (128 * SL2)
#define GSMEM_BYTES (4 * SLABH * 2)     // A[2], B[2] fp16 = 40960 B
#define STS2 136                        // ushort mirror staging stride

__device__ __forceinline__ void mma_f16(float d[4], uint32_t a0, uint32_t a1,
                                        uint32_t a2, uint32_t a3,
                                        uint32_t b0, uint32_t b1) {
    asm volatile(
        "mma.sync.aligned.m16n8k16.row.col.f32.f16.f16.f32 "
        "{%0,%1,%2,%3}, {%4,%5,%6,%7}, {%8,%9}, {%0,%1,%2,%3};"
        : "+f"(d[0]), "+f"(d[1]), "+f"(d[2]), "+f"(d[3])
        : "r"(a0), "r"(a1), "r"(a2), "r"(a3), "r"(b0), "r"(b1));
}

__device__ __forceinline__ void ldsm_x4(uint32_t& r0, uint32_t& r1, uint32_t& r2,
                                        uint32_t& r3, uint32_t addr) {
    asm volatile("ldmatrix.sync.aligned.m8n8.x4.shared.b16 {%0,%1,%2,%3}, [%4];"
                 : "=r"(r0), "=r"(r1), "=r"(r2), "=r"(r3) : "r"(addr));
}

#define CP16(dst, src) \
    asm volatile("cp.async.cg.shared.global [%0], [%1], 16;" :: "r"(dst), "l"(src))
#define CP_COMMIT() asm volatile("cp.async.commit_group;")
#define CP_WAIT(n)  asm volatile("cp.async.wait_group %0;" :: "n"(n))

__device__ __forceinline__ unsigned pack_p(float v, bool same) {
    unsigned u = __half_as_ushort(__float2half_rn(v));
    unsigned o = (u & 0x8000u) ? ((~u) & 0xFFFFu) : (u | 0x8000u);
    return (same ? 0x8000u : 0u) | (o >> 1);
}

__global__ void __launch_bounds__(256, 3) gemm_f16_kernel(const int* __restrict__ bid) {
    int bx = blockIdx.x;
    int by = blockIdx.y;
    if (bx < by) return;

    extern __shared__ __align__(16) unsigned short smh[];
    unsigned short* As[2] = {smh, smh + SLABH};
    unsigned short* Bs[2] = {smh + 2 * SLABH, smh + 3 * SLABH};

    int tid = threadIdx.x;
    int lane = tid & 31;
    int wid = tid >> 5;
    int warpM = wid & 3;
    int warpN = wid >> 2;

    int rowBase = by * 128;
    int colBase = bx * 128;

    float acc[2][8][4];
#pragma unroll
    for (int mt = 0; mt < 2; mt++)
#pragma unroll
        for (int nt = 0; nt < 8; nt++)
#pragma unroll
            for (int g = 0; g < 4; g++) acc[mt][nt][g] = 0.0f;

    int fr = lane >> 2;

    // ldmatrix lane->address components
    int aRow = lane & 15;
    int aColHalf = (lane >= 16) ? 8 : 0;
    int bSeg = lane >> 3;
    int bRow = (lane & 7) + ((bSeg >= 2) ? 8 : 0);
    int bColHalf = (bSeg & 1) ? 8 : 0;

    // cp.async loader: 2 threads per row, 16 halves (32B = 2x16B) each
    int lr = tid >> 1;
    int lh = (tid & 1) * 16;
    const __half* srcA = &g_Eh[(size_t)(rowBase + lr) * DV + lh];
    const __half* srcB = &g_Eh[(size_t)(colBase + lr) * DV + lh];
    uint32_t dA[2], dB[2];
#pragma unroll
    for (int b = 0; b < 2; b++) {
        dA[b] = (uint32_t)__cvta_generic_to_shared(&As[b][lr * SL2 + lh]);
        dB[b] = (uint32_t)__cvta_generic_to_shared(&Bs[b][lr * SL2 + lh]);
    }

    // prologue: issue chunk 0
    CP16(dA[0], srcA);      CP16(dA[0] + 16, srcA + 8);
    CP16(dB[0], srcB);      CP16(dB[0] + 16, srcB + 8);
    CP_COMMIT();

#pragma unroll 1
    for (int chunk = 0; chunk < 8; chunk++) {
        int buf = chunk & 1;
        if (chunk < 7) {
            int nb = buf ^ 1;
            const __half* sA = srcA + (chunk + 1) * 32;
            const __half* sB = srcB + (chunk + 1) * 32;
            CP16(dA[nb], sA);      CP16(dA[nb] + 16, sA + 8);
            CP16(dB[nb], sB);      CP16(dB[nb] + 16, sB + 8);
            CP_COMMIT();
            CP_WAIT(1);
        } else {
            CP_WAIT(0);
        }
        __syncthreads();

        uint32_t aBase = (uint32_t)__cvta_generic_to_shared(As[buf]);
        uint32_t bBase = (uint32_t)__cvta_generic_to_shared(Bs[buf]);
#pragma unroll
        for (int ks = 0; ks < 2; ks++) {
            int kk = ks * 16;
            uint32_t aF[2][4];
#pragma unroll
            for (int mt = 0; mt < 2; mt++) {
                int m = warpM * 32 + mt * 16;
                uint32_t addr = aBase + (uint32_t)(((m + aRow) * SL2 + kk + aColHalf) * 2);
                ldsm_x4(aF[mt][0], aF[mt][1], aF[mt][2], aF[mt][3], addr);
            }
#pragma unroll
            for (int p = 0; p < 4; p++) {
                int n0 = warpN * 64 + p * 16;
                uint32_t addr = bBase + (uint32_t)(((n0 + bRow) * SL2 + kk + bColHalf) * 2);
                uint32_t b0, b1, b2, b3;
                ldsm_x4(b0, b1, b2, b3, addr);
#pragma unroll
                for (int mt = 0; mt < 2; mt++) {
                    mma_f16(acc[mt][p * 2],     aF[mt][0], aF[mt][1], aF[mt][2], aF[mt][3], b0, b1);
                    mma_f16(acc[mt][p * 2 + 1], aF[mt][0], aF[mt][1], aF[mt][2], aF[mt][3], b2, b3);
                }
            }
        }
        __syncthreads();
    }

    // ---- direct write: packed 16-bit keys (covers diag tile fully) ----
    int c2 = (lane & 3) * 2;
#pragma unroll
    for (int mt = 0; mt < 2; mt++) {
        int row = rowBase + warpM * 32 + mt * 16 + fr;
        int br0 = __ldg(&bid[row]);
        int br1 = __ldg(&bid[row + 8]);
#pragma unroll
        for (int nt = 0; nt < 8; nt++) {
            int col = colBase + warpN * 64 + nt * 8 + c2;
            int bc0 = __ldg(&bid[col]);
            int bc1 = __ldg(&bid[col + 1]);
            unsigned p00 = pack_p(acc[mt][nt][0], bc0 == br0);
            unsigned p01 = pack_p(acc[mt][nt][1], bc1 == br0);
            unsigned p10 = pack_p(acc[mt][nt][2], bc0 == br1);
            unsigned p11 = pack_p(acc[mt][nt][3], bc1 == br1);
            *(uint32_t*)&g_p16[(size_t)row * NV + col] = p00 | (p01 << 16);
            *(uint32_t*)&g_p16[(size_t)(row + 8) * NV + col] = p10 | (p11 << 16);
        }
    }

    // ---- mirror write (bx > by): stage packed keys (flag/value symmetric) ----
    if (bx > by) {
        unsigned short* smT = smh;
#pragma unroll 1
        for (int half = 0; half < 2; half++) {
            __syncthreads();
            if (warpN == half) {
#pragma unroll
                for (int mt = 0; mt < 2; mt++) {
                    int row = rowBase + warpM * 32 + mt * 16 + fr;
                    int br0 = __ldg(&bid[row]);
                    int br1 = __ldg(&bid[row + 8]);
                    int lrr = warpM * 32 + mt * 16 + fr;
#pragma unroll
                    for (int nt = 0; nt < 8; nt++) {
                        int col = colBase + half * 64 + nt * 8 + c2;
                        int bc0 = __ldg(&bid[col]);
                        int bc1 = __ldg(&bid[col + 1]);
                        int lc = nt * 8 + c2;
                        smT[lc * STS2 + lrr]           = (unsigned short)pack_p(acc[mt][nt][0], bc0 == br0);
                        smT[(lc + 1) * STS2 + lrr]     = (unsigned short)pack_p(acc[mt][nt][1], bc1 == br0);
                        smT[lc * STS2 + lrr + 8]       = (unsigned short)pack_p(acc[mt][nt][2], bc0 == br1);
                        smT[(lc + 1) * STS2 + lrr + 8] = (unsigned short)pack_p(acc[mt][nt][3], bc1 == br1);
                    }
                }
            }
            __syncthreads();
#pragma unroll
            for (int ii = 0; ii < 4; ii++) {
                int it = tid + ii * 256;
                int c = it >> 4;
                int g = it & 15;
                int j = colBase + half * 64 + c;
                uint4 v = *(uint4*)&smT[c * STS2 + g * 8];
                *(uint4*)&g_p16[(size_t)j * NV + rowBase + g * 8] = v;
            }
        }
    }
}

// ============================================================================
// Phase 2: coarse tournament top-k on packed 16-bit keys (unchanged)
// ============================================================================
__device__ __forceinline__ unsigned f2ord(float f) {
    unsigned b = __float_as_uint(f);
    return (b & 0x80000000u) ? ~b : (b | 0x80000000u);
}

__global__ void __launch_bounds__(256) topk_kernel() {
    int i = blockIdx.x;
    int tid = threadIdx.x;
    int lane = tid & 31;
    int wid = tid >> 5;

    __shared__ unsigned short sp[NV];
    __shared__ unsigned cm0[64], cm1[64];
    __shared__ int chosen[NC];

    const uint4* row = (const uint4*)&g_p16[(size_t)i * NV];
    for (int t = tid; t < NV / 8; t += 256) ((uint4*)sp)[t] = __ldg(&row[t]);
    __syncthreads();

#pragma unroll
    for (int cc = 0; cc < 8; cc++) {
        int c = wid * 8 + cc;
        int j1 = c * 64 + lane;
        int j2 = j1 + 32;
        unsigned k1 = ((unsigned)sp[j1] << 13) | (unsigned)(NV - j1);
        unsigned k2 = ((unsigned)sp[j2] << 13) | (unsigned)(NV - j2);
        unsigned m0 = __reduce_max_sync(0xffffffffu, k1 > k2 ? k1 : k2);
        unsigned x1 = k1 ^ FB, x2 = k2 ^ FB;
        unsigned m1 = __reduce_max_sync(0xffffffffu, x1 > x2 ? x1 : x2);
        if (lane == 0) { cm0[c] = m0; cm1[c] = m1; }
    }
    __syncthreads();

    if (wid == 0) {
#pragma unroll 1
        for (int phase = 0; phase < 2; phase++) {
            unsigned* cm = phase ? cm1 : cm0;
            unsigned xm = phase ? FB : 0u;
            int cnt  = phase ? NE : NI;
            int base = phase ? NI : 0;
#pragma unroll 1
            for (int t = 0; t < cnt; t++) {
                unsigned a = cm[lane];
                unsigned b = cm[lane + 32];
                unsigned m = __reduce_max_sync(0xffffffffu, a > b ? a : b);
                int j = NV - (int)(m & 0x1FFFu);
                int c = j >> 6;
                if (lane == 0) {
                    chosen[base + t] = j;
                    sp[j] = 0x8000;
                }
                __syncwarp();
                int j1 = c * 64 + lane;
                int j2 = j1 + 32;
                unsigned k1 = (((unsigned)sp[j1] << 13) | (unsigned)(NV - j1)) ^ xm;
                unsigned k2 = (((unsigned)sp[j2] << 13) | (unsigned)(NV - j2)) ^ xm;
                unsigned rm = __reduce_max_sync(0xffffffffu, k1 > k2 ? k1 : k2);
                if (lane == 0) cm[c] = rm;
                __syncwarp();
            }
        }
    }
    __syncthreads();

    if (tid < NC) g_cand[i * NC + tid] = chosen[tid];
}

// ============================================================================
// Phase 3: EXACT rescore (k-ascending sequential fmaf == reference chain).
// ============================================================================
__global__ void __launch_bounds__(256) rescore_kernel(const float* __restrict__ E) {
    int tid = threadIdx.x;
    int grp = tid >> 6;
    int sub = tid & 63;
    int row = blockIdx.x * 4 + grp;

    __shared__ float4 EiS[4][64];
    __shared__ int    candS[4][NC];
    __shared__ ull    keyS[4][NC];
    __shared__ int    knnS[4][NSEL];

    EiS[grp][sub] = __ldg((const float4*)&E[(size_t)row * DV] + sub);
    if (sub < NC) candS[grp][sub] = g_cand[row * NC + sub];
    __syncthreads();

    if (sub < NC) {
        int j = candS[grp][sub];
        const float4* Ej4 = (const float4*)&E[(size_t)j * DV];
        const float* Ei = (const float*)&EiS[grp][0];
        float acc = 0.0f;
#pragma unroll 4
        for (int k4 = 0; k4 < 64; k4++) {
            float4 b = __ldg(&Ej4[k4]);
            acc = fmaf(Ei[k4 * 4 + 0], b.x, acc);
            acc = fmaf(Ei[k4 * 4 + 1], b.y, acc);
            acc = fmaf(Ei[k4 * 4 + 2], b.z, acc);
            acc = fmaf(Ei[k4 * 4 + 3], b.w, acc);
        }
        keyS[grp][sub] = ((ull)f2ord(acc) << 13) | (unsigned)(NV - j);
    }
    __syncthreads();

    if (sub < NC) {
        int lo = (sub < NI) ? 0 : NI;
        int hi = (sub < NI) ? NI : NC;
        ull mykey = keyS[grp][sub];
        int r = 0;
        for (int u = lo; u < hi; u++)
            if (keyS[grp][u] > mykey) r++;
        int j = candS[grp][sub];
        if (sub < NI) {
            if (r >= 1 && r <= TK) knnS[grp][r - 1] = j;
        } else {
            if (r < TKI) knnS[grp][TK + r] = j;
        }
    }
    __syncthreads();

    if (sub < NSEL) g_knn[row * NSEL + sub] = knnS[grp][sub];

    unsigned b0 = 0, b1 = 0;
    int w0 = sub * 2;
#pragma unroll
    for (int t = 0; t < NSEL; t++) {
        int j = knnS[grp][t];
        int wi = j >> 5;
        unsigned bit = 1u << (j & 31);
        if (wi == w0) b0 |= bit;
        if (wi == w0 + 1) b1 |= bit;
    }
    g_bits[row * NW + w0] = b0;
    g_bits[row * NW + w0 + 1] = b1;
}

// ============================================================================
// Phase 4: mutual check -> scatter locality + all_close
// ============================================================================
__global__ void __launch_bounds__(256) finalize_kernel(
    const float* __restrict__ adj, const int* __restrict__ cl,
    float* __restrict__ out) {
    int id = blockIdx.x * blockDim.x + threadIdx.x;
    if (id >= NV * NSEL) return;
    int i = id / NSEL;
    int j = g_knn[id];

    bool mut = (j != i) && ((g_bits[j * NW + (i >> 5)] >> (i & 31)) & 1u);
    if (mut) out[(size_t)i * NV + j] = adj[(size_t)i * NV + j];

    bool ac = mut;
    if (!ac) {
        ac = true;
#pragma unroll
        for (int m = 0; m < MLAB; m++)
            if (cl[m * NV + i] != cl[m * NV + j]) ac = false;
    }
    out[(size_t)NV * NV + id] = ac ? 1.0f : 0.0f;
}

// ============================================================================
extern "C" void kernel_launch(void* const* d_in, const int* in_sizes, int n_in,
                              void* d_out, int out_size) {
    const float* adj = (const float*)d_in[0];
    const float* E   = (const float*)d_in[1];
    const int*   bid = (const int*)d_in[2];
    const int*   cl  = (const int*)d_in[3];
    float* out = (float*)d_out;

    cudaFuncSetAttribute(gemm_f16_kernel, cudaFuncAttributeMaxDynamicSharedMemorySize,
                         GSMEM_BYTES);

    cudaMemsetAsync(out, 0, (size_t)NV * NV * sizeof(float));
    conv_kernel<<<512, 256>>>(E);
    dim3 grid(NV / 128, NV / 128);
    gemm_f16_kernel<<<grid, 256, GSMEM_BYTES>>>(bid);
    topk_kernel<<<NV, 256>>>();
    rescore_kernel<<<NV / 4, 256>>>(E);
    finalize_kernel<<<(NV * NSEL + 255) / 256, 256>>>(adj, cl, out);
}

// round 15
// speedup vs baseline: 1.0449x; 1.0449x over previous
#include <cuda_runtime.h>
#include <cuda_fp16.h>
#include <cstdint>
#include <math_constants.h>

#define NV   4096
#define DV   256
#define TK   20
#define TKI  10
#define NSEL 30
#define MLAB 5
#define NW   (NV/32)
#define NI   26
#define NE   14
#define NC   (NI + NE)
#define FB   (1u << 28)

typedef unsigned long long ull;

// -------- scratch (static device globals; no allocation) --------
__device__ unsigned short g_p16[(size_t)NV * NV];  // 32 MB packed coarse keys
__device__ int      g_knn[NV * NSEL];
__device__ unsigned g_bits[NV * NW];

// ============================================================================
// Phase 1: coarse sim via fp16 mma.sync m16n8k16 + ldmatrix, double-buffered,
// one sync per chunk (R13 version — best measured). Packs 16-bit keys.
// ============================================================================
#define SL2 40
#define SLABH (128 * SL2)
#define GSMEM_BYTES (4 * SLABH * 2)     // 40960 B
#define STS2 136

__device__ __forceinline__ uint32_t h2u(__half2 h) { return *(uint32_t*)&h; }

__device__ __forceinline__ void mma_f16(float d[4], uint32_t a0, uint32_t a1,
                                        uint32_t a2, uint32_t a3,
                                        uint32_t b0, uint32_t b1) {
    asm volatile(
        "mma.sync.aligned.m16n8k16.row.col.f32.f16.f16.f32 "
        "{%0,%1,%2,%3}, {%4,%5,%6,%7}, {%8,%9}, {%0,%1,%2,%3};"
        : "+f"(d[0]), "+f"(d[1]), "+f"(d[2]), "+f"(d[3])
        : "r"(a0), "r"(a1), "r"(a2), "r"(a3), "r"(b0), "r"(b1));
}

__device__ __forceinline__ void ldsm_x4(uint32_t& r0, uint32_t& r1, uint32_t& r2,
                                        uint32_t& r3, uint32_t addr) {
    asm volatile("ldmatrix.sync.aligned.m8n8.x4.shared.b16 {%0,%1,%2,%3}, [%4];"
                 : "=r"(r0), "=r"(r1), "=r"(r2), "=r"(r3) : "r"(addr));
}

__device__ __forceinline__ unsigned pack_p(float v, bool same) {
    unsigned u = __half_as_ushort(__float2half_rn(v));
    unsigned o = (u & 0x8000u) ? ((~u) & 0xFFFFu) : (u | 0x8000u);
    return (same ? 0x8000u : 0u) | (o >> 1);
}

__global__ void __launch_bounds__(256, 2) gemm_f16_kernel(const float* __restrict__ E,
                                                          const int* __restrict__ bid) {
    int bx = blockIdx.x;
    int by = blockIdx.y;
    if (bx < by) return;

    extern __shared__ __align__(16) unsigned short smh[];
    unsigned short* As[2] = {smh, smh + SLABH};
    unsigned short* Bs[2] = {smh + 2 * SLABH, smh + 3 * SLABH};

    int tid = threadIdx.x;
    int lane = tid & 31;
    int wid = tid >> 5;
    int warpM = wid & 3;
    int warpN = wid >> 2;

    int rowBase = by * 128;
    int colBase = bx * 128;

    float acc[2][8][4];
#pragma unroll
    for (int mt = 0; mt < 2; mt++)
#pragma unroll
        for (int nt = 0; nt < 8; nt++)
#pragma unroll
            for (int g = 0; g < 4; g++) acc[mt][nt][g] = 0.0f;

    int fr = lane >> 2;

    int aRow = lane & 15;
    int aColHalf = (lane >= 16) ? 8 : 0;
    int bSeg = lane >> 3;
    int bRow = (lane & 7) + ((bSeg >= 2) ? 8 : 0);
    int bColHalf = (bSeg & 1) ? 8 : 0;

    int lr = tid >> 1;
    int lq16 = (tid & 1) * 16;
    const float4* gA = (const float4*)&E[(size_t)(rowBase + lr) * DV] + (tid & 1) * 4;
    const float4* gB = (const float4*)&E[(size_t)(colBase + lr) * DV] + (tid & 1) * 4;

    float4 pa[4], pb[4];
#pragma unroll
    for (int q = 0; q < 4; q++) { pa[q] = __ldg(gA + q); pb[q] = __ldg(gB + q); }

    {
        uint4 u;
        u.x = h2u(__floats2half2_rn(pa[0].x, pa[0].y));
        u.y = h2u(__floats2half2_rn(pa[0].z, pa[0].w));
        u.z = h2u(__floats2half2_rn(pa[1].x, pa[1].y));
        u.w = h2u(__floats2half2_rn(pa[1].z, pa[1].w));
        *(uint4*)&As[0][lr * SL2 + lq16] = u;
        u.x = h2u(__floats2half2_rn(pa[2].x, pa[2].y));
        u.y = h2u(__floats2half2_rn(pa[2].z, pa[2].w));
        u.z = h2u(__floats2half2_rn(pa[3].x, pa[3].y));
        u.w = h2u(__floats2half2_rn(pa[3].z, pa[3].w));
        *(uint4*)&As[0][lr * SL2 + lq16 + 8] = u;
        u.x = h2u(__floats2half2_rn(pb[0].x, pb[0].y));
        u.y = h2u(__floats2half2_rn(pb[0].z, pb[0].w));
        u.z = h2u(__floats2half2_rn(pb[1].x, pb[1].y));
        u.w = h2u(__floats2half2_rn(pb[1].z, pb[1].w));
        *(uint4*)&Bs[0][lr * SL2 + lq16] = u;
        u.x = h2u(__floats2half2_rn(pb[2].x, pb[2].y));
        u.y = h2u(__floats2half2_rn(pb[2].z, pb[2].w));
        u.z = h2u(__floats2half2_rn(pb[3].x, pb[3].y));
        u.w = h2u(__floats2half2_rn(pb[3].z, pb[3].w));
        *(uint4*)&Bs[0][lr * SL2 + lq16 + 8] = u;
    }
    __syncthreads();

#pragma unroll 1
    for (int chunk = 0; chunk < 8; chunk++) {
        int buf = chunk & 1;
        if (chunk < 7) {
            int koff = (chunk + 1) * 8;
#pragma unroll
            for (int q = 0; q < 4; q++) {
                pa[q] = __ldg(gA + koff + q);
                pb[q] = __ldg(gB + koff + q);
            }
        }

        const unsigned short* Ah = As[buf];
        const unsigned short* Bh = Bs[buf];
        uint32_t aBase = (uint32_t)__cvta_generic_to_shared(Ah);
        uint32_t bBase = (uint32_t)__cvta_generic_to_shared(Bh);
#pragma unroll
        for (int ks = 0; ks < 2; ks++) {
            int kk = ks * 16;
            uint32_t aF[2][4];
#pragma unroll
            for (int mt = 0; mt < 2; mt++) {
                int m = warpM * 32 + mt * 16;
                uint32_t addr = aBase + (uint32_t)(((m + aRow) * SL2 + kk + aColHalf) * 2);
                ldsm_x4(aF[mt][0], aF[mt][1], aF[mt][2], aF[mt][3], addr);
            }
#pragma unroll
            for (int p = 0; p < 4; p++) {
                int n0 = warpN * 64 + p * 16;
                uint32_t addr = bBase + (uint32_t)(((n0 + bRow) * SL2 + kk + bColHalf) * 2);
                uint32_t b0, b1, b2, b3;
                ldsm_x4(b0, b1, b2, b3, addr);
#pragma unroll
                for (int mt = 0; mt < 2; mt++) {
                    mma_f16(acc[mt][p * 2],     aF[mt][0], aF[mt][1], aF[mt][2], aF[mt][3], b0, b1);
                    mma_f16(acc[mt][p * 2 + 1], aF[mt][0], aF[mt][1], aF[mt][2], aF[mt][3], b2, b3);
                }
            }
        }

        if (chunk < 7) {
            int nb = buf ^ 1;
            uint4 u;
            u.x = h2u(__floats2half2_rn(pa[0].x, pa[0].y));
            u.y = h2u(__floats2half2_rn(pa[0].z, pa[0].w));
            u.z = h2u(__floats2half2_rn(pa[1].x, pa[1].y));
            u.w = h2u(__floats2half2_rn(pa[1].z, pa[1].w));
            *(uint4*)&As[nb][lr * SL2 + lq16] = u;
            u.x = h2u(__floats2half2_rn(pa[2].x, pa[2].y));
            u.y = h2u(__floats2half2_rn(pa[2].z, pa[2].w));
            u.z = h2u(__floats2half2_rn(pa[3].x, pa[3].y));
            u.w = h2u(__floats2half2_rn(pa[3].z, pa[3].w));
            *(uint4*)&As[nb][lr * SL2 + lq16 + 8] = u;
            u.x = h2u(__floats2half2_rn(pb[0].x, pb[0].y));
            u.y = h2u(__floats2half2_rn(pb[0].z, pb[0].w));
            u.z = h2u(__floats2half2_rn(pb[1].x, pb[1].y));
            u.w = h2u(__floats2half2_rn(pb[1].z, pb[1].w));
            *(uint4*)&Bs[nb][lr * SL2 + lq16] = u;
            u.x = h2u(__floats2half2_rn(pb[2].x, pb[2].y));
            u.y = h2u(__floats2half2_rn(pb[2].z, pb[2].w));
            u.z = h2u(__floats2half2_rn(pb[3].x, pb[3].y));
            u.w = h2u(__floats2half2_rn(pb[3].z, pb[3].w));
            *(uint4*)&Bs[nb][lr * SL2 + lq16 + 8] = u;
            __syncthreads();
        }
    }

    int c2 = (lane & 3) * 2;
#pragma unroll
    for (int mt = 0; mt < 2; mt++) {
        int row = rowBase + warpM * 32 + mt * 16 + fr;
        int br0 = __ldg(&bid[row]);
        int br1 = __ldg(&bid[row + 8]);
#pragma unroll
        for (int nt = 0; nt < 8; nt++) {
            int col = colBase + warpN * 64 + nt * 8 + c2;
            int bc0 = __ldg(&bid[col]);
            int bc1 = __ldg(&bid[col + 1]);
            unsigned p00 = pack_p(acc[mt][nt][0], bc0 == br0);
            unsigned p01 = pack_p(acc[mt][nt][1], bc1 == br0);
            unsigned p10 = pack_p(acc[mt][nt][2], bc0 == br1);
            unsigned p11 = pack_p(acc[mt][nt][3], bc1 == br1);
            *(uint32_t*)&g_p16[(size_t)row * NV + col] = p00 | (p01 << 16);
            *(uint32_t*)&g_p16[(size_t)(row + 8) * NV + col] = p10 | (p11 << 16);
        }
    }

    if (bx > by) {
        unsigned short* smT = smh;
#pragma unroll 1
        for (int half = 0; half < 2; half++) {
            __syncthreads();
            if (warpN == half) {
#pragma unroll
                for (int mt = 0; mt < 2; mt++) {
                    int row = rowBase + warpM * 32 + mt * 16 + fr;
                    int br0 = __ldg(&bid[row]);
                    int br1 = __ldg(&bid[row + 8]);
                    int lrr = warpM * 32 + mt * 16 + fr;
#pragma unroll
                    for (int nt = 0; nt < 8; nt++) {
                        int col = colBase + half * 64 + nt * 8 + c2;
                        int bc0 = __ldg(&bid[col]);
                        int bc1 = __ldg(&bid[col + 1]);
                        int lc = nt * 8 + c2;
                        smT[lc * STS2 + lrr]           = (unsigned short)pack_p(acc[mt][nt][0], bc0 == br0);
                        smT[(lc + 1) * STS2 + lrr]     = (unsigned short)pack_p(acc[mt][nt][1], bc1 == br0);
                        smT[lc * STS2 + lrr + 8]       = (unsigned short)pack_p(acc[mt][nt][2], bc0 == br1);
                        smT[(lc + 1) * STS2 + lrr + 8] = (unsigned short)pack_p(acc[mt][nt][3], bc1 == br1);
                    }
                }
            }
            __syncthreads();
#pragma unroll
            for (int ii = 0; ii < 4; ii++) {
                int it = tid + ii * 256;
                int c = it >> 4;
                int g = it & 15;
                int j = colBase + half * 64 + c;
                uint4 v = *(uint4*)&smT[c * STS2 + g * 8];
                *(uint4*)&g_p16[(size_t)j * NV + rowBase + g * 8] = v;
            }
        }
    }
}

// ============================================================================
// Phase 2 (FUSED): tournament candidate selection + EXACT sequential rescore
// + exact rank + knn/bitset emit, one block per row. The 40 serial FMA chains
// overlap with other blocks' memory phases on the same SM.
// ============================================================================
__device__ __forceinline__ unsigned f2ord(float f) {
    unsigned b = __float_as_uint(f);
    return (b & 0x80000000u) ? ~b : (b | 0x80000000u);
}

__global__ void __launch_bounds__(256) topk_rescore_kernel(const float* __restrict__ E) {
    int i = blockIdx.x;
    int tid = threadIdx.x;
    int lane = tid & 31;
    int wid = tid >> 5;

    __shared__ unsigned short sp[NV];      // 8 KB packed coarse keys
    __shared__ unsigned cm0[64], cm1[64];
    __shared__ int chosen[NC];
    __shared__ __align__(16) float Ei[DV]; // 1 KB row embedding
    __shared__ ull keyS[NC];
    __shared__ int knnS[NSEL];

    // load packed keys + row embedding
    const uint4* row = (const uint4*)&g_p16[(size_t)i * NV];
    for (int t = tid; t < NV / 8; t += 256) ((uint4*)sp)[t] = __ldg(&row[t]);
    if (tid < 64) ((float4*)Ei)[tid] = __ldg((const float4*)&E[(size_t)i * DV] + tid);
    __syncthreads();

    // dual-phase chunk maxima, one pass
#pragma unroll
    for (int cc = 0; cc < 8; cc++) {
        int c = wid * 8 + cc;
        int j1 = c * 64 + lane;
        int j2 = j1 + 32;
        unsigned k1 = ((unsigned)sp[j1] << 13) | (unsigned)(NV - j1);
        unsigned k2 = ((unsigned)sp[j2] << 13) | (unsigned)(NV - j2);
        unsigned m0 = __reduce_max_sync(0xffffffffu, k1 > k2 ? k1 : k2);
        unsigned x1 = k1 ^ FB, x2 = k2 ^ FB;
        unsigned m1 = __reduce_max_sync(0xffffffffu, x1 > x2 ? x1 : x2);
        if (lane == 0) { cm0[c] = m0; cm1[c] = m1; }
    }
    __syncthreads();

    // warp 0 extracts NI intra + NE inter candidates
    if (wid == 0) {
#pragma unroll 1
        for (int phase = 0; phase < 2; phase++) {
            unsigned* cm = phase ? cm1 : cm0;
            unsigned xm = phase ? FB : 0u;
            int cnt  = phase ? NE : NI;
            int base = phase ? NI : 0;
#pragma unroll 1
            for (int t = 0; t < cnt; t++) {
                unsigned a = cm[lane];
                unsigned b = cm[lane + 32];
                unsigned m = __reduce_max_sync(0xffffffffu, a > b ? a : b);
                int j = NV - (int)(m & 0x1FFFu);
                int c = j >> 6;
                if (lane == 0) {
                    chosen[base + t] = j;
                    sp[j] = 0x8000;
                }
                __syncwarp();
                int j1 = c * 64 + lane;
                int j2 = j1 + 32;
                unsigned k1 = (((unsigned)sp[j1] << 13) | (unsigned)(NV - j1)) ^ xm;
                unsigned k2 = (((unsigned)sp[j2] << 13) | (unsigned)(NV - j2)) ^ xm;
                unsigned rm = __reduce_max_sync(0xffffffffu, k1 > k2 ? k1 : k2);
                if (lane == 0) cm[c] = rm;
                __syncwarp();
            }
        }
    }
    __syncthreads();

    // EXACT rescore: k-ascending sequential fmaf (== proven reference chain)
    if (tid < NC) {
        int j = chosen[tid];
        const float4* Ej4 = (const float4*)&E[(size_t)j * DV];
        float acc = 0.0f;
#pragma unroll 4
        for (int k4 = 0; k4 < 64; k4++) {
            float4 b = __ldg(&Ej4[k4]);
            acc = fmaf(Ei[k4 * 4 + 0], b.x, acc);
            acc = fmaf(Ei[k4 * 4 + 1], b.y, acc);
            acc = fmaf(Ei[k4 * 4 + 2], b.z, acc);
            acc = fmaf(Ei[k4 * 4 + 3], b.w, acc);
        }
        keyS[tid] = ((ull)f2ord(acc) << 13) | (unsigned)(NV - j);
    }
    __syncthreads();

    // exact rank within phase
    if (tid < NC) {
        int lo = (tid < NI) ? 0 : NI;
        int hi = (tid < NI) ? NI : NC;
        ull mykey = keyS[tid];
        int r = 0;
        for (int u = lo; u < hi; u++)
            if (keyS[u] > mykey) r++;
        int j = chosen[tid];
        if (tid < NI) {
            if (r >= 1 && r <= TK) knnS[r - 1] = j;
        } else {
            if (r < TKI) knnS[TK + r] = j;
        }
    }
    __syncthreads();

    if (tid < NSEL) g_knn[i * NSEL + tid] = knnS[tid];

    // membership bitset: threads 0..127 own one word each
    if (tid < NW) {
        unsigned w = 0;
#pragma unroll
        for (int t = 0; t < NSEL; t++) {
            int j = knnS[t];
            if ((j >> 5) == tid) w |= 1u << (j & 31);
        }
        g_bits[i * NW + tid] = w;
    }
}

// ============================================================================
// Phase 3: mutual check -> scatter locality + all_close
// ============================================================================
__global__ void __launch_bounds__(256) finalize_kernel(
    const float* __restrict__ adj, const int* __restrict__ cl,
    float* __restrict__ out) {
    int id = blockIdx.x * blockDim.x + threadIdx.x;
    if (id >= NV * NSEL) return;
    int i = id / NSEL;
    int j = g_knn[id];

    bool mut = (j != i) && ((g_bits[j * NW + (i >> 5)] >> (i & 31)) & 1u);
    if (mut) out[(size_t)i * NV + j] = adj[(size_t)i * NV + j];

    bool ac = mut;
    if (!ac) {
        ac = true;
#pragma unroll
        for (int m = 0; m < MLAB; m++)
            if (cl[m * NV + i] != cl[m * NV + j]) ac = false;
    }
    out[(size_t)NV * NV + id] = ac ? 1.0f : 0.0f;
}

// ============================================================================
extern "C" void kernel_launch(void* const* d_in, const int* in_sizes, int n_in,
                              void* d_out, int out_size) {
    const float* adj = (const float*)d_in[0];
    const float* E   = (const float*)d_in[1];
    const int*   bid = (const int*)d_in[2];
    const int*   cl  = (const int*)d_in[3];
    float* out = (float*)d_out;

    cudaFuncSetAttribute(gemm_f16_kernel, cudaFuncAttributeMaxDynamicSharedMemorySize,
                         GSMEM_BYTES);

    cudaMemsetAsync(out, 0, (size_t)NV * NV * sizeof(float));
    dim3 grid(NV / 128, NV / 128);
    gemm_f16_kernel<<<grid, 256, GSMEM_BYTES>>>(E, bid);
    topk_rescore_kernel<<<NV, 256>>>(E);
    finalize_kernel<<<(NV * NSEL + 255) / 256, 256>>>(adj, cl, out);
}

// round 16
// speedup vs baseline: 1.0974x; 1.0502x over previous
#include <cuda_runtime.h>
#include <cuda_fp16.h>
#include <cstdint>
#include <math_constants.h>

#define NV   4096
#define DV   256
#define TK   20
#define TKI  10
#define NSEL 30
#define MLAB 5
#define NW   (NV/32)
#define NI   26
#define NE   14
#define NC   (NI + NE)
#define FB   (1u << 28)
#define RSTR 260                       // rescore staging row stride (floats)

typedef unsigned long long ull;

// -------- scratch (static device globals; no allocation) --------
__device__ unsigned short g_p16[(size_t)NV * NV];  // 32 MB packed coarse keys
__device__ int      g_knn[NV * NSEL];
__device__ unsigned g_bits[NV * NW];

// ============================================================================
// Phase 1: coarse sim via fp16 mma.sync m16n8k16 + ldmatrix (R13 mainloop).
// Dead CTAs (bx < by) zero the 64MB locality output region instead of exiting.
// ============================================================================
#define SL2 40
#define SLABH (128 * SL2)
#define GSMEM_BYTES (4 * SLABH * 2)     // 40960 B
#define STS2 136

__device__ __forceinline__ uint32_t h2u(__half2 h) { return *(uint32_t*)&h; }

__device__ __forceinline__ void mma_f16(float d[4], uint32_t a0, uint32_t a1,
                                        uint32_t a2, uint32_t a3,
                                        uint32_t b0, uint32_t b1) {
    asm volatile(
        "mma.sync.aligned.m16n8k16.row.col.f32.f16.f16.f32 "
        "{%0,%1,%2,%3}, {%4,%5,%6,%7}, {%8,%9}, {%0,%1,%2,%3};"
        : "+f"(d[0]), "+f"(d[1]), "+f"(d[2]), "+f"(d[3])
        : "r"(a0), "r"(a1), "r"(a2), "r"(a3), "r"(b0), "r"(b1));
}

__device__ __forceinline__ void ldsm_x4(uint32_t& r0, uint32_t& r1, uint32_t& r2,
                                        uint32_t& r3, uint32_t addr) {
    asm volatile("ldmatrix.sync.aligned.m8n8.x4.shared.b16 {%0,%1,%2,%3}, [%4];"
                 : "=r"(r0), "=r"(r1), "=r"(r2), "=r"(r3) : "r"(addr));
}

__device__ __forceinline__ unsigned pack_p(float v, bool same) {
    unsigned u = __half_as_ushort(__float2half_rn(v));
    unsigned o = (u & 0x8000u) ? ((~u) & 0xFFFFu) : (u | 0x8000u);
    return (same ? 0x8000u : 0u) | (o >> 1);
}

__global__ void __launch_bounds__(256, 2) gemm_f16_kernel(const float* __restrict__ E,
                                                          const int* __restrict__ bid,
                                                          float* __restrict__ out) {
    int bx = blockIdx.x;
    int by = blockIdx.y;

    // -------- dead CTAs: zero the locality output slice --------
    if (bx < by) {
        int idx = (by * (by - 1)) / 2 + bx;            // 0..495
        const size_t total4 = (size_t)NV * NV / 4;     // float4 count
        size_t per = (total4 + 495) / 496;
        size_t s = (size_t)idx * per;
        size_t e = s + per; if (e > total4) e = total4;
        float4 z = make_float4(0.f, 0.f, 0.f, 0.f);
        for (size_t t = s + threadIdx.x; t < e; t += 256)
            ((float4*)out)[t] = z;
        return;
    }

    extern __shared__ __align__(16) unsigned short smh[];
    unsigned short* As[2] = {smh, smh + SLABH};
    unsigned short* Bs[2] = {smh + 2 * SLABH, smh + 3 * SLABH};

    int tid = threadIdx.x;
    int lane = tid & 31;
    int wid = tid >> 5;
    int warpM = wid & 3;
    int warpN = wid >> 2;

    int rowBase = by * 128;
    int colBase = bx * 128;

    float acc[2][8][4];
#pragma unroll
    for (int mt = 0; mt < 2; mt++)
#pragma unroll
        for (int nt = 0; nt < 8; nt++)
#pragma unroll
            for (int g = 0; g < 4; g++) acc[mt][nt][g] = 0.0f;

    int fr = lane >> 2;

    int aRow = lane & 15;
    int aColHalf = (lane >= 16) ? 8 : 0;
    int bSeg = lane >> 3;
    int bRow = (lane & 7) + ((bSeg >= 2) ? 8 : 0);
    int bColHalf = (bSeg & 1) ? 8 : 0;

    int lr = tid >> 1;
    int lq16 = (tid & 1) * 16;
    const float4* gA = (const float4*)&E[(size_t)(rowBase + lr) * DV] + (tid & 1) * 4;
    const float4* gB = (const float4*)&E[(size_t)(colBase + lr) * DV] + (tid & 1) * 4;

    float4 pa[4], pb[4];
#pragma unroll
    for (int q = 0; q < 4; q++) { pa[q] = __ldg(gA + q); pb[q] = __ldg(gB + q); }

    {
        uint4 u;
        u.x = h2u(__floats2half2_rn(pa[0].x, pa[0].y));
        u.y = h2u(__floats2half2_rn(pa[0].z, pa[0].w));
        u.z = h2u(__floats2half2_rn(pa[1].x, pa[1].y));
        u.w = h2u(__floats2half2_rn(pa[1].z, pa[1].w));
        *(uint4*)&As[0][lr * SL2 + lq16] = u;
        u.x = h2u(__floats2half2_rn(pa[2].x, pa[2].y));
        u.y = h2u(__floats2half2_rn(pa[2].z, pa[2].w));
        u.z = h2u(__floats2half2_rn(pa[3].x, pa[3].y));
        u.w = h2u(__floats2half2_rn(pa[3].z, pa[3].w));
        *(uint4*)&As[0][lr * SL2 + lq16 + 8] = u;
        u.x = h2u(__floats2half2_rn(pb[0].x, pb[0].y));
        u.y = h2u(__floats2half2_rn(pb[0].z, pb[0].w));
        u.z = h2u(__floats2half2_rn(pb[1].x, pb[1].y));
        u.w = h2u(__floats2half2_rn(pb[1].z, pb[1].w));
        *(uint4*)&Bs[0][lr * SL2 + lq16] = u;
        u.x = h2u(__floats2half2_rn(pb[2].x, pb[2].y));
        u.y = h2u(__floats2half2_rn(pb[2].z, pb[2].w));
        u.z = h2u(__floats2half2_rn(pb[3].x, pb[3].y));
        u.w = h2u(__floats2half2_rn(pb[3].z, pb[3].w));
        *(uint4*)&Bs[0][lr * SL2 + lq16 + 8] = u;
    }
    __syncthreads();

#pragma unroll 1
    for (int chunk = 0; chunk < 8; chunk++) {
        int buf = chunk & 1;
        if (chunk < 7) {
            int koff = (chunk + 1) * 8;
#pragma unroll
            for (int q = 0; q < 4; q++) {
                pa[q] = __ldg(gA + koff + q);
                pb[q] = __ldg(gB + koff + q);
            }
        }

        const unsigned short* Ah = As[buf];
        const unsigned short* Bh = Bs[buf];
        uint32_t aBase = (uint32_t)__cvta_generic_to_shared(Ah);
        uint32_t bBase = (uint32_t)__cvta_generic_to_shared(Bh);
#pragma unroll
        for (int ks = 0; ks < 2; ks++) {
            int kk = ks * 16;
            uint32_t aF[2][4];
#pragma unroll
            for (int mt = 0; mt < 2; mt++) {
                int m = warpM * 32 + mt * 16;
                uint32_t addr = aBase + (uint32_t)(((m + aRow) * SL2 + kk + aColHalf) * 2);
                ldsm_x4(aF[mt][0], aF[mt][1], aF[mt][2], aF[mt][3], addr);
            }
#pragma unroll
            for (int p = 0; p < 4; p++) {
                int n0 = warpN * 64 + p * 16;
                uint32_t addr = bBase + (uint32_t)(((n0 + bRow) * SL2 + kk + bColHalf) * 2);
                uint32_t b0, b1, b2, b3;
                ldsm_x4(b0, b1, b2, b3, addr);
#pragma unroll
                for (int mt = 0; mt < 2; mt++) {
                    mma_f16(acc[mt][p * 2],     aF[mt][0], aF[mt][1], aF[mt][2], aF[mt][3], b0, b1);
                    mma_f16(acc[mt][p * 2 + 1], aF[mt][0], aF[mt][1], aF[mt][2], aF[mt][3], b2, b3);
                }
            }
        }

        if (chunk < 7) {
            int nb = buf ^ 1;
            uint4 u;
            u.x = h2u(__floats2half2_rn(pa[0].x, pa[0].y));
            u.y = h2u(__floats2half2_rn(pa[0].z, pa[0].w));
            u.z = h2u(__floats2half2_rn(pa[1].x, pa[1].y));
            u.w = h2u(__floats2half2_rn(pa[1].z, pa[1].w));
            *(uint4*)&As[nb][lr * SL2 + lq16] = u;
            u.x = h2u(__floats2half2_rn(pa[2].x, pa[2].y));
            u.y = h2u(__floats2half2_rn(pa[2].z, pa[2].w));
            u.z = h2u(__floats2half2_rn(pa[3].x, pa[3].y));
            u.w = h2u(__floats2half2_rn(pa[3].z, pa[3].w));
            *(uint4*)&As[nb][lr * SL2 + lq16 + 8] = u;
            u.x = h2u(__floats2half2_rn(pb[0].x, pb[0].y));
            u.y = h2u(__floats2half2_rn(pb[0].z, pb[0].w));
            u.z = h2u(__floats2half2_rn(pb[1].x, pb[1].y));
            u.w = h2u(__floats2half2_rn(pb[1].z, pb[1].w));
            *(uint4*)&Bs[nb][lr * SL2 + lq16] = u;
            u.x = h2u(__floats2half2_rn(pb[2].x, pb[2].y));
            u.y = h2u(__floats2half2_rn(pb[2].z, pb[2].w));
            u.z = h2u(__floats2half2_rn(pb[3].x, pb[3].y));
            u.w = h2u(__floats2half2_rn(pb[3].z, pb[3].w));
            *(uint4*)&Bs[nb][lr * SL2 + lq16 + 8] = u;
            __syncthreads();
        }
    }

    int c2 = (lane & 3) * 2;
#pragma unroll
    for (int mt = 0; mt < 2; mt++) {
        int row = rowBase + warpM * 32 + mt * 16 + fr;
        int br0 = __ldg(&bid[row]);
        int br1 = __ldg(&bid[row + 8]);
#pragma unroll
        for (int nt = 0; nt < 8; nt++) {
            int col = colBase + warpN * 64 + nt * 8 + c2;
            int bc0 = __ldg(&bid[col]);
            int bc1 = __ldg(&bid[col + 1]);
            unsigned p00 = pack_p(acc[mt][nt][0], bc0 == br0);
            unsigned p01 = pack_p(acc[mt][nt][1], bc1 == br0);
            unsigned p10 = pack_p(acc[mt][nt][2], bc0 == br1);
            unsigned p11 = pack_p(acc[mt][nt][3], bc1 == br1);
            *(uint32_t*)&g_p16[(size_t)row * NV + col] = p00 | (p01 << 16);
            *(uint32_t*)&g_p16[(size_t)(row + 8) * NV + col] = p10 | (p11 << 16);
        }
    }

    if (bx > by) {
        unsigned short* smT = smh;
#pragma unroll 1
        for (int half = 0; half < 2; half++) {
            __syncthreads();
            if (warpN == half) {
#pragma unroll
                for (int mt = 0; mt < 2; mt++) {
                    int row = rowBase + warpM * 32 + mt * 16 + fr;
                    int br0 = __ldg(&bid[row]);
                    int br1 = __ldg(&bid[row + 8]);
                    int lrr = warpM * 32 + mt * 16 + fr;
#pragma unroll
                    for (int nt = 0; nt < 8; nt++) {
                        int col = colBase + half * 64 + nt * 8 + c2;
                        int bc0 = __ldg(&bid[col]);
                        int bc1 = __ldg(&bid[col + 1]);
                        int lc = nt * 8 + c2;
                        smT[lc * STS2 + lrr]           = (unsigned short)pack_p(acc[mt][nt][0], bc0 == br0);
                        smT[(lc + 1) * STS2 + lrr]     = (unsigned short)pack_p(acc[mt][nt][1], bc1 == br0);
                        smT[lc * STS2 + lrr + 8]       = (unsigned short)pack_p(acc[mt][nt][2], bc0 == br1);
                        smT[(lc + 1) * STS2 + lrr + 8] = (unsigned short)pack_p(acc[mt][nt][3], bc1 == br1);
                    }
                }
            }
            __syncthreads();
#pragma unroll
            for (int ii = 0; ii < 4; ii++) {
                int it = tid + ii * 256;
                int c = it >> 4;
                int g = it & 15;
                int j = colBase + half * 64 + c;
                uint4 v = *(uint4*)&smT[c * STS2 + g * 8];
                *(uint4*)&g_p16[(size_t)j * NV + rowBase + g * 8] = v;
            }
        }
    }
}

// ============================================================================
// Phase 2 (FUSED): tournament selection + staged coalesced candidate load +
// EXACT sequential rescore + exact rank + knn/bitset emit.
// ============================================================================
__device__ __forceinline__ unsigned f2ord(float f) {
    unsigned b = __float_as_uint(f);
    return (b & 0x80000000u) ? ~b : (b | 0x80000000u);
}

__global__ void __launch_bounds__(256) topk_rescore_kernel(const float* __restrict__ E) {
    int i = blockIdx.x;
    int tid = threadIdx.x;
    int lane = tid & 31;
    int wid = tid >> 5;

    // staging buffer (40 rows x 260-float stride = 41.6KB) overlays the
    // packed-key array (8KB, dead after extraction)
    __shared__ __align__(16) float stage[NC * RSTR];
    unsigned short* sp = (unsigned short*)stage;
    __shared__ unsigned cm0[64], cm1[64];
    __shared__ int chosen[NC];
    __shared__ __align__(16) float Ei[DV];
    __shared__ ull keyS[NC];
    __shared__ int knnS[NSEL];

    const uint4* row = (const uint4*)&g_p16[(size_t)i * NV];
    for (int t = tid; t < NV / 8; t += 256) ((uint4*)sp)[t] = __ldg(&row[t]);
    if (tid < 64) ((float4*)Ei)[tid] = __ldg((const float4*)&E[(size_t)i * DV] + tid);
    __syncthreads();

    // dual-phase chunk maxima, one pass
#pragma unroll
    for (int cc = 0; cc < 8; cc++) {
        int c = wid * 8 + cc;
        int j1 = c * 64 + lane;
        int j2 = j1 + 32;
        unsigned k1 = ((unsigned)sp[j1] << 13) | (unsigned)(NV - j1);
        unsigned k2 = ((unsigned)sp[j2] << 13) | (unsigned)(NV - j2);
        unsigned m0 = __reduce_max_sync(0xffffffffu, k1 > k2 ? k1 : k2);
        unsigned x1 = k1 ^ FB, x2 = k2 ^ FB;
        unsigned m1 = __reduce_max_sync(0xffffffffu, x1 > x2 ? x1 : x2);
        if (lane == 0) { cm0[c] = m0; cm1[c] = m1; }
    }
    __syncthreads();

    // warp 0 extracts candidates
    if (wid == 0) {
#pragma unroll 1
        for (int phase = 0; phase < 2; phase++) {
            unsigned* cm = phase ? cm1 : cm0;
            unsigned xm = phase ? FB : 0u;
            int cnt  = phase ? NE : NI;
            int base = phase ? NI : 0;
#pragma unroll 1
            for (int t = 0; t < cnt; t++) {
                unsigned a = cm[lane];
                unsigned b = cm[lane + 32];
                unsigned m = __reduce_max_sync(0xffffffffu, a > b ? a : b);
                int j = NV - (int)(m & 0x1FFFu);
                int c = j >> 6;
                if (lane == 0) {
                    chosen[base + t] = j;
                    sp[j] = 0x8000;
                }
                __syncwarp();
                int j1 = c * 64 + lane;
                int j2 = j1 + 32;
                unsigned k1 = (((unsigned)sp[j1] << 13) | (unsigned)(NV - j1)) ^ xm;
                unsigned k2 = (((unsigned)sp[j2] << 13) | (unsigned)(NV - j2)) ^ xm;
                unsigned rm = __reduce_max_sync(0xffffffffu, k1 > k2 ? k1 : k2);
                if (lane == 0) cm[c] = rm;
                __syncwarp();
            }
        }
    }
    __syncthreads();   // extraction done; sp region now dead -> reuse as stage

    // staged coalesced load of all candidate rows (nL=1 per LDG)
    for (int t = tid; t < NC * 64; t += 256) {
        int c = t >> 6;
        int q = t & 63;
        int j = chosen[c];
        float4 v = __ldg((const float4*)&E[(size_t)j * DV] + q);
        *(float4*)&stage[c * RSTR + q * 4] = v;
    }
    __syncthreads();

    // EXACT rescore from smem (values bit-identical to global)
    if (tid < NC) {
        const float* Er = &stage[tid * RSTR];
        float acc = 0.0f;
#pragma unroll 4
        for (int k4 = 0; k4 < 64; k4++) {
            float4 b = *(const float4*)&Er[k4 * 4];
            acc = fmaf(Ei[k4 * 4 + 0], b.x, acc);
            acc = fmaf(Ei[k4 * 4 + 1], b.y, acc);
            acc = fmaf(Ei[k4 * 4 + 2], b.z, acc);
            acc = fmaf(Ei[k4 * 4 + 3], b.w, acc);
        }
        keyS[tid] = ((ull)f2ord(acc) << 13) | (unsigned)(NV - chosen[tid]);
    }
    __syncthreads();

    if (tid < NC) {
        int lo = (tid < NI) ? 0 : NI;
        int hi = (tid < NI) ? NI : NC;
        ull mykey = keyS[tid];
        int r = 0;
        for (int u = lo; u < hi; u++)
            if (keyS[u] > mykey) r++;
        int j = chosen[tid];
        if (tid < NI) {
            if (r >= 1 && r <= TK) knnS[r - 1] = j;
        } else {
            if (r < TKI) knnS[TK + r] = j;
        }
    }
    __syncthreads();

    if (tid < NSEL) g_knn[i * NSEL + tid] = knnS[tid];

    if (tid < NW) {
        unsigned w = 0;
#pragma unroll
        for (int t = 0; t < NSEL; t++) {
            int j = knnS[t];
            if ((j >> 5) == tid) w |= 1u << (j & 31);
        }
        g_bits[i * NW + tid] = w;
    }
}

// ============================================================================
// Phase 3: mutual check -> scatter locality + all_close
// ============================================================================
__global__ void __launch_bounds__(256) finalize_kernel(
    const float* __restrict__ adj, const int* __restrict__ cl,
    float* __restrict__ out) {
    int id = blockIdx.x * blockDim.x + threadIdx.x;
    if (id >= NV * NSEL) return;
    int i = id / NSEL;
    int j = g_knn[id];

    bool mut = (j != i) && ((g_bits[j * NW + (i >> 5)] >> (i & 31)) & 1u);
    if (mut) out[(size_t)i * NV + j] = adj[(size_t)i * NV + j];

    bool ac = mut;
    if (!ac) {
        ac = true;
#pragma unroll
        for (int m = 0; m < MLAB; m++)
            if (cl[m * NV + i] != cl[m * NV + j]) ac = false;
    }
    out[(size_t)NV * NV + id] = ac ? 1.0f : 0.0f;
}

// ============================================================================
extern "C" void kernel_launch(void* const* d_in, const int* in_sizes, int n_in,
                              void* d_out, int out_size) {
    const float* adj = (const float*)d_in[0];
    const float* E   = (const float*)d_in[1];
    const int*   bid = (const int*)d_in[2];
    const int*   cl  = (const int*)d_in[3];
    float* out = (float*)d_out;

    cudaFuncSetAttribute(gemm_f16_kernel, cudaFuncAttributeMaxDynamicSharedMemorySize,
                         GSMEM_BYTES);

    dim3 grid(NV / 128, NV / 128);
    gemm_f16_kernel<<<grid, 256, GSMEM_BYTES>>>(E, bid, out);
    topk_rescore_kernel<<<NV, 256>>>(E);
    finalize_kernel<<<(NV * NSEL + 255) / 256, 256>>>(adj, cl, out);
}

// round 17
// speedup vs baseline: 1.1545x; 1.0520x over previous
#include <cuda_runtime.h>
#include <cuda_fp16.h>
#include <cstdint>
#include <math_constants.h>

#define NV   4096
#define DV   256
#define TK   20
#define TKI  10
#define NSEL 30
#define MLAB 5
#define NW   (NV/32)
#define NI   26
#define NE   14
#define NC   (NI + NE)
#define FB   (1u << 28)
#define RSTR 260                       // rescore staging row stride (floats)

typedef unsigned long long ull;

// -------- scratch (static device globals; no allocation) --------
__device__ unsigned short g_p16[(size_t)NV * NV];  // 32 MB packed coarse keys
__device__ int      g_knn[NV * NSEL];
__device__ unsigned g_bits[NV * NW];

// ============================================================================
// Phase 1: coarse sim via fp16 mma.sync m16n8k16 + ldmatrix (R13 mainloop).
// Dead CTAs (bx < by) zero the 64MB locality output region instead of exiting.
// ============================================================================
#define SL2 40
#define SLABH (128 * SL2)
#define GSMEM_BYTES (4 * SLABH * 2)     // 40960 B
#define STS2 136

__device__ __forceinline__ uint32_t h2u(__half2 h) { return *(uint32_t*)&h; }

__device__ __forceinline__ void mma_f16(float d[4], uint32_t a0, uint32_t a1,
                                        uint32_t a2, uint32_t a3,
                                        uint32_t b0, uint32_t b1) {
    asm volatile(
        "mma.sync.aligned.m16n8k16.row.col.f32.f16.f16.f32 "
        "{%0,%1,%2,%3}, {%4,%5,%6,%7}, {%8,%9}, {%0,%1,%2,%3};"
        : "+f"(d[0]), "+f"(d[1]), "+f"(d[2]), "+f"(d[3])
        : "r"(a0), "r"(a1), "r"(a2), "r"(a3), "r"(b0), "r"(b1));
}

__device__ __forceinline__ void ldsm_x4(uint32_t& r0, uint32_t& r1, uint32_t& r2,
                                        uint32_t& r3, uint32_t addr) {
    asm volatile("ldmatrix.sync.aligned.m8n8.x4.shared.b16 {%0,%1,%2,%3}, [%4];"
                 : "=r"(r0), "=r"(r1), "=r"(r2), "=r"(r3) : "r"(addr));
}

__device__ __forceinline__ unsigned pack_p(float v, bool same) {
    unsigned u = __half_as_ushort(__float2half_rn(v));
    unsigned o = (u & 0x8000u) ? ((~u) & 0xFFFFu) : (u | 0x8000u);
    return (same ? 0x8000u : 0u) | (o >> 1);
}

__global__ void __launch_bounds__(256, 2) gemm_f16_kernel(const float* __restrict__ E,
                                                          const int* __restrict__ bid,
                                                          float* __restrict__ out) {
    int bx = blockIdx.x;
    int by = blockIdx.y;

    // -------- dead CTAs: zero the locality output slice --------
    if (bx < by) {
        int idx = (by * (by - 1)) / 2 + bx;            // 0..495
        const size_t total4 = (size_t)NV * NV / 4;     // float4 count
        size_t per = (total4 + 495) / 496;
        size_t s = (size_t)idx * per;
        size_t e = s + per; if (e > total4) e = total4;
        float4 z = make_float4(0.f, 0.f, 0.f, 0.f);
        for (size_t t = s + threadIdx.x; t < e; t += 256)
            ((float4*)out)[t] = z;
        return;
    }

    extern __shared__ __align__(16) unsigned short smh[];
    unsigned short* As[2] = {smh, smh + SLABH};
    unsigned short* Bs[2] = {smh + 2 * SLABH, smh + 3 * SLABH};

    int tid = threadIdx.x;
    int lane = tid & 31;
    int wid = tid >> 5;
    int warpM = wid & 3;
    int warpN = wid >> 2;

    int rowBase = by * 128;
    int colBase = bx * 128;

    float acc[2][8][4];
#pragma unroll
    for (int mt = 0; mt < 2; mt++)
#pragma unroll
        for (int nt = 0; nt < 8; nt++)
#pragma unroll
            for (int g = 0; g < 4; g++) acc[mt][nt][g] = 0.0f;

    int fr = lane >> 2;

    int aRow = lane & 15;
    int aColHalf = (lane >= 16) ? 8 : 0;
    int bSeg = lane >> 3;
    int bRow = (lane & 7) + ((bSeg >= 2) ? 8 : 0);
    int bColHalf = (bSeg & 1) ? 8 : 0;

    int lr = tid >> 1;
    int lq16 = (tid & 1) * 16;
    const float4* gA = (const float4*)&E[(size_t)(rowBase + lr) * DV] + (tid & 1) * 4;
    const float4* gB = (const float4*)&E[(size_t)(colBase + lr) * DV] + (tid & 1) * 4;

    float4 pa[4], pb[4];
#pragma unroll
    for (int q = 0; q < 4; q++) { pa[q] = __ldg(gA + q); pb[q] = __ldg(gB + q); }

    {
        uint4 u;
        u.x = h2u(__floats2half2_rn(pa[0].x, pa[0].y));
        u.y = h2u(__floats2half2_rn(pa[0].z, pa[0].w));
        u.z = h2u(__floats2half2_rn(pa[1].x, pa[1].y));
        u.w = h2u(__floats2half2_rn(pa[1].z, pa[1].w));
        *(uint4*)&As[0][lr * SL2 + lq16] = u;
        u.x = h2u(__floats2half2_rn(pa[2].x, pa[2].y));
        u.y = h2u(__floats2half2_rn(pa[2].z, pa[2].w));
        u.z = h2u(__floats2half2_rn(pa[3].x, pa[3].y));
        u.w = h2u(__floats2half2_rn(pa[3].z, pa[3].w));
        *(uint4*)&As[0][lr * SL2 + lq16 + 8] = u;
        u.x = h2u(__floats2half2_rn(pb[0].x, pb[0].y));
        u.y = h2u(__floats2half2_rn(pb[0].z, pb[0].w));
        u.z = h2u(__floats2half2_rn(pb[1].x, pb[1].y));
        u.w = h2u(__floats2half2_rn(pb[1].z, pb[1].w));
        *(uint4*)&Bs[0][lr * SL2 + lq16] = u;
        u.x = h2u(__floats2half2_rn(pb[2].x, pb[2].y));
        u.y = h2u(__floats2half2_rn(pb[2].z, pb[2].w));
        u.z = h2u(__floats2half2_rn(pb[3].x, pb[3].y));
        u.w = h2u(__floats2half2_rn(pb[3].z, pb[3].w));
        *(uint4*)&Bs[0][lr * SL2 + lq16 + 8] = u;
    }
    __syncthreads();

#pragma unroll 1
    for (int chunk = 0; chunk < 8; chunk++) {
        int buf = chunk & 1;
        if (chunk < 7) {
            int koff = (chunk + 1) * 8;
#pragma unroll
            for (int q = 0; q < 4; q++) {
                pa[q] = __ldg(gA + koff + q);
                pb[q] = __ldg(gB + koff + q);
            }
        }

        const unsigned short* Ah = As[buf];
        const unsigned short* Bh = Bs[buf];
        uint32_t aBase = (uint32_t)__cvta_generic_to_shared(Ah);
        uint32_t bBase = (uint32_t)__cvta_generic_to_shared(Bh);
#pragma unroll
        for (int ks = 0; ks < 2; ks++) {
            int kk = ks * 16;
            uint32_t aF[2][4];
#pragma unroll
            for (int mt = 0; mt < 2; mt++) {
                int m = warpM * 32 + mt * 16;
                uint32_t addr = aBase + (uint32_t)(((m + aRow) * SL2 + kk + aColHalf) * 2);
                ldsm_x4(aF[mt][0], aF[mt][1], aF[mt][2], aF[mt][3], addr);
            }
#pragma unroll
            for (int p = 0; p < 4; p++) {
                int n0 = warpN * 64 + p * 16;
                uint32_t addr = bBase + (uint32_t)(((n0 + bRow) * SL2 + kk + bColHalf) * 2);
                uint32_t b0, b1, b2, b3;
                ldsm_x4(b0, b1, b2, b3, addr);
#pragma unroll
                for (int mt = 0; mt < 2; mt++) {
                    mma_f16(acc[mt][p * 2],     aF[mt][0], aF[mt][1], aF[mt][2], aF[mt][3], b0, b1);
                    mma_f16(acc[mt][p * 2 + 1], aF[mt][0], aF[mt][1], aF[mt][2], aF[mt][3], b2, b3);
                }
            }
        }

        if (chunk < 7) {
            int nb = buf ^ 1;
            uint4 u;
            u.x = h2u(__floats2half2_rn(pa[0].x, pa[0].y));
            u.y = h2u(__floats2half2_rn(pa[0].z, pa[0].w));
            u.z = h2u(__floats2half2_rn(pa[1].x, pa[1].y));
            u.w = h2u(__floats2half2_rn(pa[1].z, pa[1].w));
            *(uint4*)&As[nb][lr * SL2 + lq16] = u;
            u.x = h2u(__floats2half2_rn(pa[2].x, pa[2].y));
            u.y = h2u(__floats2half2_rn(pa[2].z, pa[2].w));
            u.z = h2u(__floats2half2_rn(pa[3].x, pa[3].y));
            u.w = h2u(__floats2half2_rn(pa[3].z, pa[3].w));
            *(uint4*)&As[nb][lr * SL2 + lq16 + 8] = u;
            u.x = h2u(__floats2half2_rn(pb[0].x, pb[0].y));
            u.y = h2u(__floats2half2_rn(pb[0].z, pb[0].w));
            u.z = h2u(__floats2half2_rn(pb[1].x, pb[1].y));
            u.w = h2u(__floats2half2_rn(pb[1].z, pb[1].w));
            *(uint4*)&Bs[nb][lr * SL2 + lq16] = u;
            u.x = h2u(__floats2half2_rn(pb[2].x, pb[2].y));
            u.y = h2u(__floats2half2_rn(pb[2].z, pb[2].w));
            u.z = h2u(__floats2half2_rn(pb[3].x, pb[3].y));
            u.w = h2u(__floats2half2_rn(pb[3].z, pb[3].w));
            *(uint4*)&Bs[nb][lr * SL2 + lq16 + 8] = u;
            __syncthreads();
        }
    }

    int c2 = (lane & 3) * 2;
#pragma unroll
    for (int mt = 0; mt < 2; mt++) {
        int row = rowBase + warpM * 32 + mt * 16 + fr;
        int br0 = __ldg(&bid[row]);
        int br1 = __ldg(&bid[row + 8]);
#pragma unroll
        for (int nt = 0; nt < 8; nt++) {
            int col = colBase + warpN * 64 + nt * 8 + c2;
            int bc0 = __ldg(&bid[col]);
            int bc1 = __ldg(&bid[col + 1]);
            unsigned p00 = pack_p(acc[mt][nt][0], bc0 == br0);
            unsigned p01 = pack_p(acc[mt][nt][1], bc1 == br0);
            unsigned p10 = pack_p(acc[mt][nt][2], bc0 == br1);
            unsigned p11 = pack_p(acc[mt][nt][3], bc1 == br1);
            *(uint32_t*)&g_p16[(size_t)row * NV + col] = p00 | (p01 << 16);
            *(uint32_t*)&g_p16[(size_t)(row + 8) * NV + col] = p10 | (p11 << 16);
        }
    }

    if (bx > by) {
        unsigned short* smT = smh;
#pragma unroll 1
        for (int half = 0; half < 2; half++) {
            __syncthreads();
            if (warpN == half) {
#pragma unroll
                for (int mt = 0; mt < 2; mt++) {
                    int row = rowBase + warpM * 32 + mt * 16 + fr;
                    int br0 = __ldg(&bid[row]);
                    int br1 = __ldg(&bid[row + 8]);
                    int lrr = warpM * 32 + mt * 16 + fr;
#pragma unroll
                    for (int nt = 0; nt < 8; nt++) {
                        int col = colBase + half * 64 + nt * 8 + c2;
                        int bc0 = __ldg(&bid[col]);
                        int bc1 = __ldg(&bid[col + 1]);
                        int lc = nt * 8 + c2;
                        smT[lc * STS2 + lrr]           = (unsigned short)pack_p(acc[mt][nt][0], bc0 == br0);
                        smT[(lc + 1) * STS2 + lrr]     = (unsigned short)pack_p(acc[mt][nt][1], bc1 == br0);
                        smT[lc * STS2 + lrr + 8]       = (unsigned short)pack_p(acc[mt][nt][2], bc0 == br1);
                        smT[(lc + 1) * STS2 + lrr + 8] = (unsigned short)pack_p(acc[mt][nt][3], bc1 == br1);
                    }
                }
            }
            __syncthreads();
#pragma unroll
            for (int ii = 0; ii < 4; ii++) {
                int it = tid + ii * 256;
                int c = it >> 4;
                int g = it & 15;
                int j = colBase + half * 64 + c;
                uint4 v = *(uint4*)&smT[c * STS2 + g * 8];
                *(uint4*)&g_p16[(size_t)j * NV + rowBase + g * 8] = v;
            }
        }
    }
}

// ============================================================================
// Phase 2 (FUSED): DUAL-WARP tournament (warp0=intra, warp1=inter, provably
// independent) + staged coalesced candidate load + EXACT sequential rescore.
// ============================================================================
__device__ __forceinline__ unsigned f2ord(float f) {
    unsigned b = __float_as_uint(f);
    return (b & 0x80000000u) ? ~b : (b | 0x80000000u);
}

__global__ void __launch_bounds__(256) topk_rescore_kernel(const float* __restrict__ E) {
    int i = blockIdx.x;
    int tid = threadIdx.x;
    int lane = tid & 31;
    int wid = tid >> 5;

    __shared__ __align__(16) float stage[NC * RSTR];
    unsigned short* sp = (unsigned short*)stage;   // overlays stage (dead later)
    __shared__ unsigned cm0[64], cm1[64];
    __shared__ int chosen[NC];
    __shared__ __align__(16) float Ei[DV];
    __shared__ ull keyS[NC];
    __shared__ int knnS[NSEL];

    const uint4* row = (const uint4*)&g_p16[(size_t)i * NV];
    for (int t = tid; t < NV / 8; t += 256) ((uint4*)sp)[t] = __ldg(&row[t]);
    if (tid < 64) ((float4*)Ei)[tid] = __ldg((const float4*)&E[(size_t)i * DV] + tid);
    __syncthreads();

    // dual-phase chunk maxima, one pass
#pragma unroll
    for (int cc = 0; cc < 8; cc++) {
        int c = wid * 8 + cc;
        int j1 = c * 64 + lane;
        int j2 = j1 + 32;
        unsigned k1 = ((unsigned)sp[j1] << 13) | (unsigned)(NV - j1);
        unsigned k2 = ((unsigned)sp[j2] << 13) | (unsigned)(NV - j2);
        unsigned m0 = __reduce_max_sync(0xffffffffu, k1 > k2 ? k1 : k2);
        unsigned x1 = k1 ^ FB, x2 = k2 ^ FB;
        unsigned m1 = __reduce_max_sync(0xffffffffu, x1 > x2 ? x1 : x2);
        if (lane == 0) { cm0[c] = m0; cm1[c] = m1; }
    }
    __syncthreads();

    // CONCURRENT extraction: warp 0 -> intra (26), warp 1 -> inter (14).
    // Safe: phases select from disjoint flag groups; removal marker 0x8000
    // sorts below all real candidates in both orderings.
    if (wid < 2) {
        unsigned* cm = wid ? cm1 : cm0;
        unsigned xm = wid ? FB : 0u;
        int cnt  = wid ? NE : NI;
        int base = wid ? NI : 0;
#pragma unroll 1
        for (int t = 0; t < cnt; t++) {
            unsigned a = cm[lane];
            unsigned b = cm[lane + 32];
            unsigned m = __reduce_max_sync(0xffffffffu, a > b ? a : b);
            int j = NV - (int)(m & 0x1FFFu);
            int c = j >> 6;
            if (lane == 0) {
                chosen[base + t] = j;
                sp[j] = 0x8000;
            }
            __syncwarp();
            int j1 = c * 64 + lane;
            int j2 = j1 + 32;
            unsigned k1 = (((unsigned)sp[j1] << 13) | (unsigned)(NV - j1)) ^ xm;
            unsigned k2 = (((unsigned)sp[j2] << 13) | (unsigned)(NV - j2)) ^ xm;
            unsigned rm = __reduce_max_sync(0xffffffffu, k1 > k2 ? k1 : k2);
            if (lane == 0) cm[c] = rm;
            __syncwarp();
        }
    }
    __syncthreads();   // extraction done; sp region dead -> reuse as stage

    // staged coalesced load of all candidate rows (nL=1 per LDG)
    for (int t = tid; t < NC * 64; t += 256) {
        int c = t >> 6;
        int q = t & 63;
        int j = chosen[c];
        float4 v = __ldg((const float4*)&E[(size_t)j * DV] + q);
        *(float4*)&stage[c * RSTR + q * 4] = v;
    }
    __syncthreads();

    // EXACT rescore from smem (bit-identical values)
    if (tid < NC) {
        const float* Er = &stage[tid * RSTR];
        float acc = 0.0f;
#pragma unroll 4
        for (int k4 = 0; k4 < 64; k4++) {
            float4 b = *(const float4*)&Er[k4 * 4];
            acc = fmaf(Ei[k4 * 4 + 0], b.x, acc);
            acc = fmaf(Ei[k4 * 4 + 1], b.y, acc);
            acc = fmaf(Ei[k4 * 4 + 2], b.z, acc);
            acc = fmaf(Ei[k4 * 4 + 3], b.w, acc);
        }
        keyS[tid] = ((ull)f2ord(acc) << 13) | (unsigned)(NV - chosen[tid]);
    }
    __syncthreads();

    if (tid < NC) {
        int lo = (tid < NI) ? 0 : NI;
        int hi = (tid < NI) ? NI : NC;
        ull mykey = keyS[tid];
        int r = 0;
        for (int u = lo; u < hi; u++)
            if (keyS[u] > mykey) r++;
        int j = chosen[tid];
        if (tid < NI) {
            if (r >= 1 && r <= TK) knnS[r - 1] = j;
        } else {
            if (r < TKI) knnS[TK + r] = j;
        }
    }
    __syncthreads();

    if (tid < NSEL) g_knn[i * NSEL + tid] = knnS[tid];

    if (tid < NW) {
        unsigned w = 0;
#pragma unroll
        for (int t = 0; t < NSEL; t++) {
            int j = knnS[t];
            if ((j >> 5) == tid) w |= 1u << (j & 31);
        }
        g_bits[i * NW + tid] = w;
    }
}

// ============================================================================
// Phase 3: mutual check -> scatter locality + all_close
// ============================================================================
__global__ void __launch_bounds__(256) finalize_kernel(
    const float* __restrict__ adj, const int* __restrict__ cl,
    float* __restrict__ out) {
    int id = blockIdx.x * blockDim.x + threadIdx.x;
    if (id >= NV * NSEL) return;
    int i = id / NSEL;
    int j = g_knn[id];

    bool mut = (j != i) && ((g_bits[j * NW + (i >> 5)] >> (i & 31)) & 1u);
    if (mut) out[(size_t)i * NV + j] = adj[(size_t)i * NV + j];

    bool ac = mut;
    if (!ac) {
        ac = true;
#pragma unroll
        for (int m = 0; m < MLAB; m++)
            if (cl[m * NV + i] != cl[m * NV + j]) ac = false;
    }
    out[(size_t)NV * NV + id] = ac ? 1.0f : 0.0f;
}

// ============================================================================
extern "C" void kernel_launch(void* const* d_in, const int* in_sizes, int n_in,
                              void* d_out, int out_size) {
    const float* adj = (const float*)d_in[0];
    const float* E   = (const float*)d_in[1];
    const int*   bid = (const int*)d_in[2];
    const int*   cl  = (const int*)d_in[3];
    float* out = (float*)d_out;

    cudaFuncSetAttribute(gemm_f16_kernel, cudaFuncAttributeMaxDynamicSharedMemorySize,
                         GSMEM_BYTES);

    dim3 grid(NV / 128, NV / 128);
    gemm_f16_kernel<<<grid, 256, GSMEM_BYTES>>>(E, bid, out);
    topk_rescore_kernel<<<NV, 256>>>(E);
    finalize_kernel<<<(NV * NSEL + 255) / 256, 256>>>(adj, cl, out);
}